// round 1
// baseline (speedup 1.0000x reference)
#include <cuda_runtime.h>

// Problem constants (fixed by setup_inputs)
#define BQ   33
#define BBSZ 1089
#define NS   8
#define NH   8
#define NL   8
#define NCOL 512        // NL*NH*NS
#define MROW 272
#define HP   264        // NH*33 == NL*33
#define IMGPIX (NS*HP*HP)   // 557568 == BBSZ*NCOL

// ---------------- scratch (device globals; no allocation allowed) -----------
__device__ float g_X[BBSZ * NCOL];
__device__ float g_y[MROW * NCOL];
__device__ float g_r[MROW * NCOL];
__device__ float g_z[BBSZ * NCOL];       // also used as Xb and deblock output
__device__ float g_noise[BBSZ * NCOL];
__device__ float g_AtA[BBSZ * BBSZ];
__device__ float g_im[IMGPIX];
__device__ float g_t1[(size_t)NCOL * 32 * BBSZ];  // 17,842,176 floats
__device__ float g_t2[(size_t)NCOL * 32 * BBSZ];

// ---------------- blockify / unblockify -------------------------------------
// Xb[r,n] = img[s, h*33+i, l*33+j],  r=i*33+j, n=l*64+h*8+s
__global__ void blockify_input_kernel(const float* __restrict__ in, float* __restrict__ Xb) {
    int idx = blockIdx.x * blockDim.x + threadIdx.x;
    if (idx >= BBSZ * NCOL) return;
    int r = idx / NCOL, n = idx % NCOL;
    int i = r / BQ, j = r % BQ;
    int l = n / (NH * NS), h = (n / NS) % NH, s = n % NS;
    Xb[idx] = in[(s * HP + h * BQ + i) * HP + l * BQ + j];
}

__global__ void unblockify_kernel(const float* __restrict__ X, float* __restrict__ img) {
    int idx = blockIdx.x * blockDim.x + threadIdx.x;
    if (idx >= IMGPIX) return;
    int s = idx / (HP * HP);
    int rem = idx % (HP * HP);
    int R = rem / HP, C = rem % HP;
    int h = R / BQ, i = R % BQ, l = C / BQ, j = C % BQ;
    img[idx] = X[(i * BQ + j) * NCOL + (l * (NH * NS) + h * NS + s)];
}

// X = blockify(img - db)
__global__ void blockify_sub_kernel(const float* __restrict__ img,
                                    const float* __restrict__ db,
                                    float* __restrict__ X) {
    int idx = blockIdx.x * blockDim.x + threadIdx.x;
    if (idx >= IMGPIX) return;
    int s = idx / (HP * HP);
    int rem = idx % (HP * HP);
    int R = rem / HP, C = rem % HP;
    int h = R / BQ, i = R % BQ, l = C / BQ, j = C % BQ;
    X[(i * BQ + j) * NCOL + (l * (NH * NS) + h * NS + s)] = img[idx] - db[idx];
}

// ---------------- generic tiled fp32 GEMM with fused epilogues --------------
// C[M,N] = epilogue(acc)  where acc = opA(A) @ B
//  transA=0: A is [M,K] row-major with lda
//  transA=1: A element (m,k) = A[k*lda + m]
//  B is [K,N] row-major (ldb = N), C is [M,N] (ldc = N)
// epi: 0: C = acc
//      1: C = E1 - acc
//      2: C = step*acc + E1
//      3: C = E1 - step*acc + E2
#define GBM 64
#define GBN 64
#define GBK 16
__global__ void gemm_kernel(const float* __restrict__ A, const float* __restrict__ B,
                            float* __restrict__ C,
                            int M, int N, int K, int lda, int transA,
                            int epi, const float* __restrict__ E1,
                            const float* __restrict__ E2,
                            const float* __restrict__ stepsPtr, int stepIdx) {
    __shared__ float As[GBK][GBM];
    __shared__ float Bs[GBK][GBN + 1];
    int bm = blockIdx.y * GBM, bn = blockIdx.x * GBN;
    int tid = threadIdx.x;
    int tx = tid % 16, ty = tid / 16;

    float acc[4][4];
#pragma unroll
    for (int i = 0; i < 4; i++)
#pragma unroll
        for (int j = 0; j < 4; j++) acc[i][j] = 0.f;

    for (int k0 = 0; k0 < K; k0 += GBK) {
        if (transA) {
            for (int e = tid; e < GBM * GBK; e += 256) {
                int k = e / GBM, m = e % GBM;
                int gm = bm + m, gk = k0 + k;
                As[k][m] = (gm < M && gk < K) ? A[(size_t)gk * lda + gm] : 0.f;
            }
        } else {
            for (int e = tid; e < GBM * GBK; e += 256) {
                int m = e / GBK, k = e % GBK;
                int gm = bm + m, gk = k0 + k;
                As[k][m] = (gm < M && gk < K) ? A[(size_t)gm * lda + gk] : 0.f;
            }
        }
        for (int e = tid; e < GBK * GBN; e += 256) {
            int k = e / GBN, n = e % GBN;
            int gk = k0 + k, gn = bn + n;
            Bs[k][n] = (gk < K && gn < N) ? B[(size_t)gk * N + gn] : 0.f;
        }
        __syncthreads();
#pragma unroll
        for (int k = 0; k < GBK; k++) {
            float a[4], b[4];
#pragma unroll
            for (int i = 0; i < 4; i++) a[i] = As[k][ty * 4 + i];
#pragma unroll
            for (int j = 0; j < 4; j++) b[j] = Bs[k][tx * 4 + j];
#pragma unroll
            for (int i = 0; i < 4; i++)
#pragma unroll
                for (int j = 0; j < 4; j++) acc[i][j] += a[i] * b[j];
        }
        __syncthreads();
    }

    float step = (stepsPtr != nullptr) ? stepsPtr[stepIdx] : 0.f;
#pragma unroll
    for (int i = 0; i < 4; i++) {
        int gm = bm + ty * 4 + i;
        if (gm >= M) continue;
#pragma unroll
        for (int j = 0; j < 4; j++) {
            int gn = bn + tx * 4 + j;
            if (gn >= N) continue;
            size_t idx = (size_t)gm * N + gn;
            float v = acc[i][j];
            float o;
            if (epi == 0)      o = v;
            else if (epi == 1) o = E1[idx] - v;
            else if (epi == 2) o = step * v + E1[idx];
            else               o = E1[idx] - step * v + E2[idx];
            C[idx] = o;
        }
    }
}

// ---------------- generic 3x3 SAME conv, 33x33 tiles -------------------------
// Block: one 33x33 output tile of one image, COPB output channels.
// 363 threads, 3 pixels each. Input channel staged in smem (35x35 halo).
// inTrans: input is single-channel, stored column-major [pix, NCOL] (denoise in)
// outTrans: output is single-channel, stored column-major (denoise noise out)
template <int COPB>
__global__ void conv3x3_kernel(const float* __restrict__ in,
                               const float* __restrict__ wt,
                               const float* __restrict__ bias,
                               float* __restrict__ out,
                               int Cin, int Cout,
                               int Himg, int Wimg, int tilesX, int tilesY,
                               int relu, int inTrans, int outTrans) {
    __shared__ float s_in[35 * 35];
    __shared__ float s_w[COPB * 9];

    int tpi = tilesX * tilesY;
    int n    = blockIdx.x / tpi;
    int trem = blockIdx.x % tpi;
    int ty0 = (trem / tilesX) * BQ;
    int tx0 = (trem % tilesX) * BQ;
    int ocBase = blockIdx.y * COPB;
    int tid = threadIdx.x;

    float acc[3][COPB];
#pragma unroll
    for (int pp = 0; pp < 3; pp++)
#pragma unroll
        for (int oc = 0; oc < COPB; oc++) acc[pp][oc] = 0.f;

    for (int c = 0; c < Cin; c++) {
        __syncthreads();
        for (int q = tid; q < 35 * 35; q += 363) {
            int gi = ty0 + q / 35 - 1;
            int gj = tx0 + q % 35 - 1;
            float v = 0.f;
            if (gi >= 0 && gi < Himg && gj >= 0 && gj < Wimg) {
                if (inTrans) v = in[(size_t)(gi * Wimg + gj) * NCOL + n];
                else         v = in[((size_t)(n * Cin + c) * Himg + gi) * Wimg + gj];
            }
            s_in[q] = v;
        }
        for (int q = tid; q < COPB * 9; q += 363)
            s_w[q] = wt[((size_t)(ocBase + q / 9) * Cin + c) * 9 + (q % 9)];
        __syncthreads();

        float v[3][9];
#pragma unroll
        for (int pp = 0; pp < 3; pp++) {
            int p = tid + pp * 363;
            int i = p / BQ, j = p % BQ;
#pragma unroll
            for (int di = 0; di < 3; di++)
#pragma unroll
                for (int dj = 0; dj < 3; dj++)
                    v[pp][di * 3 + dj] = s_in[(i + di) * 35 + (j + dj)];
        }
#pragma unroll
        for (int oc = 0; oc < COPB; oc++) {
            float w[9];
#pragma unroll
            for (int r = 0; r < 9; r++) w[r] = s_w[oc * 9 + r];
#pragma unroll
            for (int pp = 0; pp < 3; pp++) {
                float s = 0.f;
#pragma unroll
                for (int r = 0; r < 9; r++) s += v[pp][r] * w[r];
                acc[pp][oc] += s;
            }
        }
    }

#pragma unroll
    for (int pp = 0; pp < 3; pp++) {
        int p = tid + pp * 363;
        int i = p / BQ, j = p % BQ;
        int gi = ty0 + i, gj = tx0 + j;
#pragma unroll
        for (int oc = 0; oc < COPB; oc++) {
            float bv = (bias != nullptr) ? bias[ocBase + oc] : 0.f;
            float v = acc[pp][oc] + bv;
            if (relu) v = fmaxf(v, 0.f);
            if (outTrans)
                out[(size_t)(gi * Wimg + gj) * NCOL + n] = v;
            else
                out[((size_t)(n * Cout + ocBase + oc) * Himg + gi) * Wimg + gj] = v;
        }
    }
}

// ---------------- host driver ------------------------------------------------
extern "C" void kernel_launch(void* const* d_in, const int* in_sizes, int n_in,
                              void* d_out, int out_size) {
    const float* inputs = (const float*)d_in[0];
    const float* A      = (const float*)d_in[1];
    const float* Q      = (const float*)d_in[2];
    const float* steps  = (const float*)d_in[3];
    const float* den_w1 = (const float*)d_in[4];
    const float* den_b1 = (const float*)d_in[5];
    const float* den_w2 = (const float*)d_in[6];
    const float* den_b2 = (const float*)d_in[7];
    const float* den_w3 = (const float*)d_in[8];
    const float* den_b3 = (const float*)d_in[9];
    const float* den_w4 = (const float*)d_in[10];
    const float* deb_w1 = (const float*)d_in[11];
    const float* deb_b1 = (const float*)d_in[12];
    const float* deb_w2 = (const float*)d_in[13];
    const float* deb_b2 = (const float*)d_in[14];
    const float* deb_w3 = (const float*)d_in[15];
    const float* deb_b3 = (const float*)d_in[16];
    const float* deb_w4 = (const float*)d_in[17];
    int layers = in_sizes[3];  // steps element count == output_layers in setup

    float *pX, *pY, *pR, *pZ, *pN, *pAtA, *pIm, *pT1, *pT2;
    cudaGetSymbolAddress((void**)&pX, g_X);
    cudaGetSymbolAddress((void**)&pY, g_y);
    cudaGetSymbolAddress((void**)&pR, g_r);
    cudaGetSymbolAddress((void**)&pZ, g_z);
    cudaGetSymbolAddress((void**)&pN, g_noise);
    cudaGetSymbolAddress((void**)&pAtA, g_AtA);
    cudaGetSymbolAddress((void**)&pIm, g_im);
    cudaGetSymbolAddress((void**)&pT1, g_t1);
    cudaGetSymbolAddress((void**)&pT2, g_t2);

    const int EW = 256;
    const int EG = (IMGPIX + EW - 1) / EW;

    dim3 gN512M272((NCOL + GBN - 1) / GBN, (MROW + GBM - 1) / GBM);   // (8,5)
    dim3 gN512M1089((NCOL + GBN - 1) / GBN, (BBSZ + GBM - 1) / GBM);  // (8,18)
    dim3 gAtA((BBSZ + GBN - 1) / GBN, (BBSZ + GBM - 1) / GBM);        // (18,18)

    // ---- init: Xb, y = A@Xb, X = Q@y, AtA = A^T@A ----
    blockify_input_kernel<<<EG, EW>>>(inputs, pZ);
    gemm_kernel<<<gN512M272, 256>>>(A, pZ, pY, MROW, NCOL, BBSZ, BBSZ, 0, 0,
                                    nullptr, nullptr, nullptr, 0);
    gemm_kernel<<<gN512M1089, 256>>>(Q, pY, pX, BBSZ, NCOL, MROW, MROW, 0, 0,
                                     nullptr, nullptr, nullptr, 0);
    gemm_kernel<<<gAtA, 256>>>(A, A, pAtA, BBSZ, BBSZ, MROW, BBSZ, 1, 0,
                               nullptr, nullptr, nullptr, 0);

    dim3 cgrid32(NCOL, 4);   // 512 tiles x 4 oc-groups of 8
    dim3 cgrid1(NCOL, 1);

    for (int n = 0; n < layers; n++) {
        // r = y - A@X
        gemm_kernel<<<gN512M272, 256>>>(A, pX, pR, MROW, NCOL, BBSZ, BBSZ, 0, 1,
                                        pY, nullptr, nullptr, 0);
        // z = step*(A^T@r) + X
        gemm_kernel<<<gN512M1089, 256>>>(A, pR, pZ, BBSZ, NCOL, MROW, BBSZ, 1, 2,
                                         pX, nullptr, steps, n);
        // denoise CNN on X (column-layout input, 512 images of 33x33)
        conv3x3_kernel<8><<<cgrid32, 363>>>(pX, den_w1 + (size_t)n * 32 * 9,
                                            den_b1 + n * 32, pT1, 1, 32,
                                            BQ, BQ, 1, 1, 1, 1, 0);
        conv3x3_kernel<8><<<cgrid32, 363>>>(pT1, den_w2 + (size_t)n * 32 * 32 * 9,
                                            den_b2 + n * 32, pT2, 32, 32,
                                            BQ, BQ, 1, 1, 1, 0, 0);
        conv3x3_kernel<8><<<cgrid32, 363>>>(pT2, den_w3 + (size_t)n * 32 * 32 * 9,
                                            den_b3 + n * 32, pT1, 32, 32,
                                            BQ, BQ, 1, 1, 1, 0, 0);
        conv3x3_kernel<1><<<cgrid1, 363>>>(pT1, den_w4 + (size_t)n * 32 * 9,
                                           nullptr, pN, 32, 1,
                                           BQ, BQ, 1, 1, 0, 0, 1);
        // X = z - step*(AtA@noise) + noise
        gemm_kernel<<<gN512M1089, 256>>>(pAtA, pN, pX, BBSZ, NCOL, BBSZ, BBSZ, 0, 3,
                                         pZ, pN, steps, n);
        // img = unblockify(X)
        unblockify_kernel<<<EG, EW>>>(pX, pIm);
        // deblock CNN on img (8 images of 264x264, 8x8 tiles of 33x33)
        conv3x3_kernel<8><<<cgrid32, 363>>>(pIm, deb_w1 + (size_t)n * 32 * 9,
                                            deb_b1 + n * 32, pT1, 1, 32,
                                            HP, HP, 8, 8, 1, 0, 0);
        conv3x3_kernel<8><<<cgrid32, 363>>>(pT1, deb_w2 + (size_t)n * 32 * 32 * 9,
                                            deb_b2 + n * 32, pT2, 32, 32,
                                            HP, HP, 8, 8, 1, 0, 0);
        conv3x3_kernel<8><<<cgrid32, 363>>>(pT2, deb_w3 + (size_t)n * 32 * 32 * 9,
                                            deb_b3 + n * 32, pT1, 32, 32,
                                            HP, HP, 8, 8, 1, 0, 0);
        conv3x3_kernel<1><<<cgrid1, 363>>>(pT1, deb_w4 + (size_t)n * 32 * 9,
                                           nullptr, pZ, 32, 1,
                                           HP, HP, 8, 8, 0, 0, 0);
        // X = blockify(img - deblock_out)
        blockify_sub_kernel<<<EG, EW>>>(pIm, pZ, pX);
    }

    unblockify_kernel<<<EG, EW>>>(pX, (float*)d_out);
}